// round 7
// baseline (speedup 1.0000x reference)
#include <cuda_runtime.h>
#include <cuda_bf16.h>
#include <cstdint>

// Problem constants
#define BB 2
#define LL 2048
#define DD 1024
#define HH 16
#define DKH 64
#define MTOT (BB*LL)   // 4096

// ---------------------------------------------------------------------------
// Scratch (no cudaMalloc allowed) — all bf16 hi/lo split pairs
// ---------------------------------------------------------------------------
__device__ __nv_bfloat16 g_xhi[MTOT*DD], g_xlo[MTOT*DD];
__device__ __nv_bfloat16 g_whi[4*DD*DD], g_wlo[4*DD*DD];
__device__ __nv_bfloat16 g_qhi[BB*HH*LL*DKH], g_qlo[BB*HH*LL*DKH];
__device__ __nv_bfloat16 g_khi[BB*HH*LL*DKH], g_klo[BB*HH*LL*DKH];
__device__ __nv_bfloat16 g_vhi[BB*HH*LL*DKH], g_vlo[BB*HH*LL*DKH];
__device__ __nv_bfloat16 g_ohi[MTOT*DD], g_olo[MTOT*DD];

__device__ __forceinline__ uint32_t smem_to_u32(const void* p) {
    uint32_t a;
    asm("{ .reg .u64 t; cvta.to.shared.u64 t, %1; cvt.u32.u64 %0, t; }" : "=r"(a) : "l"(p));
    return a;
}
#define SMEM_SWIZZLE_128B(o) ((o) ^ (((o) >> 3) & 0x70))

#define CP_ASYNC16(dst_u32, gptr) \
    asm volatile("cp.async.cg.shared.global [%0], [%1], 16;" \
                 :: "r"(dst_u32), "l"(gptr) : "memory")
#define CP_COMMIT() asm volatile("cp.async.commit_group;" ::: "memory")
#define CP_WAIT0()  asm volatile("cp.async.wait_group 0;" ::: "memory")
#define CP_WAIT1()  asm volatile("cp.async.wait_group 1;" ::: "memory")

__device__ __forceinline__ void ldmx4(uint32_t* r, uint32_t addr) {
    asm volatile("ldmatrix.sync.aligned.m8n8.x4.shared.b16 {%0,%1,%2,%3}, [%4];"
                 : "=r"(r[0]), "=r"(r[1]), "=r"(r[2]), "=r"(r[3]) : "r"(addr));
}
__device__ __forceinline__ void ldmx4t(uint32_t* r, uint32_t addr) {
    asm volatile("ldmatrix.sync.aligned.m8n8.x4.trans.shared.b16 {%0,%1,%2,%3}, [%4];"
                 : "=r"(r[0]), "=r"(r[1]), "=r"(r[2]), "=r"(r[3]) : "r"(addr));
}
__device__ __forceinline__ void mma_bf16(float* c, const uint32_t* a, const uint32_t* b) {
    asm volatile("mma.sync.aligned.m16n8k16.row.col.f32.bf16.bf16.f32 "
                 "{%0,%1,%2,%3}, {%4,%5,%6,%7}, {%8,%9}, {%0,%1,%2,%3};"
                 : "+f"(c[0]), "+f"(c[1]), "+f"(c[2]), "+f"(c[3])
                 : "r"(a[0]), "r"(a[1]), "r"(a[2]), "r"(a[3]), "r"(b[0]), "r"(b[1]));
}
__device__ __forceinline__ uint32_t pack_bf16(__nv_bfloat16 x, __nv_bfloat16 y) {
    __nv_bfloat162 h; h.x = x; h.y = y;
    uint32_t u; __builtin_memcpy(&u, &h, 4);
    return u;
}

// ---------------------------------------------------------------------------
// Fused fp32 -> bf16 hi/lo split for x + 4 weights (one launch)
// ---------------------------------------------------------------------------
__global__ void split_all(const float* __restrict__ x,
                          const float* __restrict__ wq, const float* __restrict__ wk,
                          const float* __restrict__ wv, const float* __restrict__ wo,
                          __nv_bfloat16* __restrict__ xhi, __nv_bfloat16* __restrict__ xlo,
                          __nv_bfloat16* __restrict__ whi, __nv_bfloat16* __restrict__ wlo) {
    const int bid = blockIdx.x;
    const float* src;
    __nv_bfloat16 *hi, *lo;
    int i;
    if (bid < 4096) {
        src = x; hi = xhi; lo = xlo;
        i = bid * 256 + threadIdx.x;
    } else {
        const int wsel = (bid - 4096) >> 10;
        const int lb   = (bid - 4096) & 1023;
        src = (wsel == 0) ? wq : (wsel == 1) ? wk : (wsel == 2) ? wv : wo;
        hi = whi + (size_t)wsel * DD * DD;
        lo = wlo + (size_t)wsel * DD * DD;
        i = lb * 256 + threadIdx.x;
    }
    float4 v = ((const float4*)src)[i];
    __nv_bfloat16 h0 = __float2bfloat16(v.x), h1 = __float2bfloat16(v.y);
    __nv_bfloat16 h2 = __float2bfloat16(v.z), h3 = __float2bfloat16(v.w);
    ((__nv_bfloat162*)hi)[i*2+0] = __nv_bfloat162(h0, h1);
    ((__nv_bfloat162*)hi)[i*2+1] = __nv_bfloat162(h2, h3);
    ((__nv_bfloat162*)lo)[i*2+0] = __nv_bfloat162(
        __float2bfloat16(v.x - __bfloat162float(h0)),
        __float2bfloat16(v.y - __bfloat162float(h1)));
    ((__nv_bfloat162*)lo)[i*2+1] = __nv_bfloat162(
        __float2bfloat16(v.z - __bfloat162float(h2)),
        __float2bfloat16(v.w - __bfloat162float(h3)));
}

// ---------------------------------------------------------------------------
// mma.sync bf16 GEMM, 3-term split. CTA 128x128, BK=32, 3-stage cp.async.
// smem row (128B) = [32 bf16 hi | 32 bf16 lo]; stage (32KB): A@0 B@16K.
// MODE 1: fused QKV (blockIdx.y 0..23, wsel = y>>3), bf16 hi/lo scatter.
// MODE 0: single GEMM (blockIdx.y 0..7), fp32 C row-major.
// ---------------------------------------------------------------------------
#define GEMM_SMEM (3*32768)
#define NCHUNK 32

template<int MODE>
__global__ void __launch_bounds__(256, 2) mm_gemm(
        const __nv_bfloat16* __restrict__ Ahi, const __nv_bfloat16* __restrict__ Alo,
        const __nv_bfloat16* __restrict__ WhiB, const __nv_bfloat16* __restrict__ WloB,
        const float* __restrict__ bias0, const float* __restrict__ bias1,
        const float* __restrict__ bias2, float* __restrict__ C,
        __nv_bfloat16* __restrict__ c0hi, __nv_bfloat16* __restrict__ c0lo,
        __nv_bfloat16* __restrict__ c1hi, __nv_bfloat16* __restrict__ c1lo,
        __nv_bfloat16* __restrict__ c2hi, __nv_bfloat16* __restrict__ c2lo) {
    extern __shared__ char sm[];
    const uint32_t sbase = smem_to_u32(sm);

    const int tid  = threadIdx.x;
    const int wid  = tid >> 5, lane = tid & 31;
    const int wm   = wid & 1, wn = wid >> 1;
    const int mBase = blockIdx.x * 128;

    int nBase, wsel = 0;
    const __nv_bfloat16 *Bhi, *Blo;
    const float* bias;
    if (MODE == 1) {
        wsel  = blockIdx.y >> 3;
        nBase = (blockIdx.y & 7) * 128;
        Bhi = WhiB + (size_t)wsel * DD * DD;
        Blo = WloB + (size_t)wsel * DD * DD;
        bias = (wsel == 0) ? bias0 : (wsel == 1) ? bias1 : bias2;
    } else {
        nBase = blockIdx.y * 128;
        Bhi = WhiB; Blo = WloB; bias = bias0;
    }

    float acc[4][4][4] = {};

    const int aRow = (lane & 15);
    const int aKb  = (lane >> 4) * 16;
    const int bRow = ((lane >> 4) & 1) * 8 + (lane & 7);
    const int bKb  = ((lane >> 3) & 1) * 16;

    // loader: 2 tiles x 128 rows x 8 segs(16B) = 2048 / 256 thr = 8 per thread
    auto issue_chunk = [&](int k0, int st) {
        #pragma unroll
        for (int it = 0; it < 8; it++) {
            const int u = it * 256 + tid;
            const int t = u >> 10, idx = u & 1023;
            const int row = idx >> 3, seg = idx & 7;
            const __nv_bfloat16* g;
            if (t == 0) g = ((seg < 4) ? Ahi : Alo) + (size_t)(mBase + row) * DD;
            else        g = ((seg < 4) ? Bhi : Blo) + (size_t)(nBase + row) * DD;
            const uint32_t d = sbase + st * 32768 + t * 16384
                             + SMEM_SWIZZLE_128B(row * 128 + seg * 16);
            CP_ASYNC16(d, g + k0 + (seg & 3) * 8);
        }
    };

    issue_chunk(0, 0);
    CP_COMMIT();
    issue_chunk(32, 1);
    CP_COMMIT();

    int stC = 0, stI = 2;
    for (int c = 0; c < NCHUNK; c++) {
        if (c == NCHUNK - 1) CP_WAIT0(); else CP_WAIT1();
        __syncthreads();
        if (c + 2 < NCHUNK) {
            issue_chunk((c + 2) * 32, stI);
            CP_COMMIT();
            if (++stI == 3) stI = 0;
        }
        const uint32_t sb0 = sbase + stC * 32768;
        if (++stC == 3) stC = 0;

        #pragma unroll
        for (int ks = 0; ks < 2; ks++) {
            uint32_t bh[4][2], bl[4][2];
            #pragma unroll
            for (int p = 0; p < 2; p++) {
                const uint32_t bb = (wn * 32 + p * 16 + bRow) * 128 + ks * 32 + bKb;
                uint32_t r[4];
                ldmx4(r, sb0 + 16384 + SMEM_SWIZZLE_128B(bb));
                bh[p*2+0][0] = r[0]; bh[p*2+0][1] = r[1];
                bh[p*2+1][0] = r[2]; bh[p*2+1][1] = r[3];
                ldmx4(r, sb0 + 16384 + SMEM_SWIZZLE_128B(bb + 64));
                bl[p*2+0][0] = r[0]; bl[p*2+0][1] = r[1];
                bl[p*2+1][0] = r[2]; bl[p*2+1][1] = r[3];
            }
            #pragma unroll
            for (int mf = 0; mf < 4; mf++) {
                const uint32_t ab = (wm * 64 + mf * 16 + aRow) * 128 + ks * 32 + aKb;
                uint32_t ah[4], al[4];
                ldmx4(ah, sb0 + SMEM_SWIZZLE_128B(ab));
                ldmx4(al, sb0 + SMEM_SWIZZLE_128B(ab + 64));
                #pragma unroll
                for (int nf = 0; nf < 4; nf++) {
                    mma_bf16(acc[mf][nf], ah, bh[nf]);
                    mma_bf16(acc[mf][nf], ah, bl[nf]);
                    mma_bf16(acc[mf][nf], al, bh[nf]);
                }
            }
        }
    }

    __nv_bfloat16 *Chi = nullptr, *Clo = nullptr;
    if (MODE == 1) {
        Chi = (wsel == 0) ? c0hi : (wsel == 1) ? c1hi : c2hi;
        Clo = (wsel == 0) ? c0lo : (wsel == 1) ? c1lo : c2lo;
    }

    const int rEp = lane >> 2, cEp = (lane & 3) * 2;
    #pragma unroll
    for (int mf = 0; mf < 4; mf++) {
        #pragma unroll
        for (int nf = 0; nf < 4; nf++) {
            const int m0 = mBase + wm * 64 + mf * 16 + rEp;
            const int n  = nBase + wn * 32 + nf * 8 + cEp;
            const float b0 = bias[n], b1 = bias[n + 1];
            float2 v0 = make_float2(acc[mf][nf][0] + b0, acc[mf][nf][1] + b1);
            float2 v1 = make_float2(acc[mf][nf][2] + b0, acc[mf][nf][3] + b1);
            if (MODE == 0) {
                *(float2*)(C + (size_t)m0 * DD + n) = v0;
                *(float2*)(C + (size_t)(m0 + 8) * DD + n) = v1;
            } else {
                const int h = n >> 6, dk = n & 63;
                const int b_ = m0 / LL, l0 = m0 % LL, l1 = l0 + 8;
                const size_t i0 = (((size_t)b_ * HH + h) * LL + l0) * DKH + dk;
                const size_t i1 = (((size_t)b_ * HH + h) * LL + l1) * DKH + dk;
                __nv_bfloat16 h00 = __float2bfloat16(v0.x), h01 = __float2bfloat16(v0.y);
                __nv_bfloat16 h10 = __float2bfloat16(v1.x), h11 = __float2bfloat16(v1.y);
                *(__nv_bfloat162*)(Chi + i0) = __nv_bfloat162(h00, h01);
                *(__nv_bfloat162*)(Chi + i1) = __nv_bfloat162(h10, h11);
                *(__nv_bfloat162*)(Clo + i0) = __nv_bfloat162(
                    __float2bfloat16(v0.x - __bfloat162float(h00)),
                    __float2bfloat16(v0.y - __bfloat162float(h01)));
                *(__nv_bfloat162*)(Clo + i1) = __nv_bfloat162(
                    __float2bfloat16(v1.x - __bfloat162float(h10)),
                    __float2bfloat16(v1.y - __bfloat162float(h11)));
            }
        }
    }
}

// ---------------------------------------------------------------------------
// Tensor-core causal flash attention, cp.async 2-stage K/V pipeline.
// BQ=128, BKV=64, 8 warps. Softmax in exp2 domain (scale folds log2e).
// smem: Qhi@0 Qlo@16K; stage s at 32K+s*32K: Khi@+0 Klo@+8K Vhi@+16K Vlo@+24K
// ---------------------------------------------------------------------------
#define ATT_SMEM (32768 + 2*32768)
#define SCL2 0.18033688011112042f   // (1/8) * log2(e)

__global__ void __launch_bounds__(256, 2) attn_mma(
        const __nv_bfloat16* __restrict__ Qhi, const __nv_bfloat16* __restrict__ Qlo,
        const __nv_bfloat16* __restrict__ Khi, const __nv_bfloat16* __restrict__ Klo,
        const __nv_bfloat16* __restrict__ Vhi, const __nv_bfloat16* __restrict__ Vlo,
        __nv_bfloat16* __restrict__ Ohi, __nv_bfloat16* __restrict__ Olo) {
    extern __shared__ char sm[];
    const uint32_t sb = smem_to_u32(sm);

    const int tid = threadIdx.x, wid = tid >> 5, lane = tid & 31;
    const int qb = blockIdx.x, bh = blockIdx.y;

    auto issue_kv = [&](int kb, int st) {
        #pragma unroll
        for (int it = 0; it < 8; it++) {
            const int u = it * 256 + tid;
            const int arr = u >> 9, idx = u & 511;
            const int row = idx >> 3, seg = idx & 7;
            const __nv_bfloat16* src = (arr == 0) ? Khi : (arr == 1) ? Klo
                                     : (arr == 2) ? Vhi : Vlo;
            const uint32_t d = sb + 32768 + st * 32768 + arr * 8192
                             + SMEM_SWIZZLE_128B(row * 128 + seg * 16);
            CP_ASYNC16(d, src + ((size_t)bh * LL + kb * 64 + row) * DKH + seg * 8);
        }
    };

    #pragma unroll
    for (int it = 0; it < 8; it++) {
        const int u = it * 256 + tid;
        const int arr = u >> 10, idx = u & 1023;
        const int row = idx >> 3, seg = idx & 7;
        const __nv_bfloat16* src = arr ? Qlo : Qhi;
        const uint32_t d = sb + arr * 16384 + SMEM_SWIZZLE_128B(row * 128 + seg * 16);
        CP_ASYNC16(d, src + ((size_t)bh * LL + qb * 128 + row) * DKH + seg * 8);
    }
    issue_kv(0, 0);
    CP_COMMIT();

    float s[8][4];
    float o[8][4] = {};
    float m0 = -1e30f, m1 = -1e30f, l0 = 0.0f, l1 = 0.0f;

    const int r0 = lane >> 2;
    const int ig0 = qb * 128 + wid * 16 + r0, ig1 = ig0 + 8;
    const int aRow = lane & 15;
    const int aKb  = (lane >> 4) * 16;
    const int bRow = ((lane >> 4) & 1) * 8 + (lane & 7);
    const int bKb  = ((lane >> 3) & 1) * 16;
    const int vseg = lane >> 3;
    const int vr   = (vseg & 1) * 8 + (lane & 7);
    const int vcB  = (vseg >> 1) * 16;

    const int kbmax = 2 * qb + 1;
    for (int kb = 0; kb <= kbmax; kb++) {
        CP_WAIT0();
        __syncthreads();
        if (kb < kbmax) {
            issue_kv(kb + 1, (kb + 1) & 1);
            CP_COMMIT();
        }

        const bool skip = (kb * 64 > qb * 128 + wid * 16 + 15);
        if (!skip) {
            const uint32_t kvb = sb + 32768 + (kb & 1) * 32768;

            // ---- S = Q K^T (3-term split) ----
            #pragma unroll
            for (int nf = 0; nf < 8; nf++)
                s[nf][0] = s[nf][1] = s[nf][2] = s[nf][3] = 0.0f;
            #pragma unroll
            for (int ks = 0; ks < 4; ks++) {
                const uint32_t aoff = SMEM_SWIZZLE_128B((wid * 16 + aRow) * 128 + ks * 32 + aKb);
                uint32_t ah[4], al[4];
                ldmx4(ah, sb + aoff);
                ldmx4(al, sb + 16384 + aoff);
                #pragma unroll
                for (int p = 0; p < 4; p++) {
                    const uint32_t boff = SMEM_SWIZZLE_128B((p * 16 + bRow) * 128 + ks * 32 + bKb);
                    uint32_t rh[4], rl[4];
                    ldmx4(rh, kvb + boff);
                    ldmx4(rl, kvb + 8192 + boff);
                    mma_bf16(s[2*p],   ah, rh);
                    mma_bf16(s[2*p],   ah, rl);
                    mma_bf16(s[2*p],   al, rh);
                    mma_bf16(s[2*p+1], ah, rh + 2);
                    mma_bf16(s[2*p+1], ah, rl + 2);
                    mma_bf16(s[2*p+1], al, rh + 2);
                }
            }

            // ---- online softmax in exp2 domain (quad shuffles) ----
            const bool needMask = (kb >= 2 * qb);
            float mx0 = -1e30f, mx1 = -1e30f;
            #pragma unroll
            for (int nf = 0; nf < 8; nf++) {
                #pragma unroll
                for (int c = 0; c < 4; c++) {
                    float v = s[nf][c] * SCL2;
                    if (needMask) {
                        const int jg = kb * 64 + nf * 8 + 2 * (lane & 3) + (c & 1);
                        if (jg > ((c < 2) ? ig0 : ig1)) v = -1e30f;
                    }
                    s[nf][c] = v;
                }
                mx0 = fmaxf(mx0, fmaxf(s[nf][0], s[nf][1]));
                mx1 = fmaxf(mx1, fmaxf(s[nf][2], s[nf][3]));
            }
            mx0 = fmaxf(mx0, __shfl_xor_sync(~0u, mx0, 1));
            mx0 = fmaxf(mx0, __shfl_xor_sync(~0u, mx0, 2));
            mx1 = fmaxf(mx1, __shfl_xor_sync(~0u, mx1, 1));
            mx1 = fmaxf(mx1, __shfl_xor_sync(~0u, mx1, 2));
            const float mn0 = fmaxf(m0, mx0), mn1 = fmaxf(m1, mx1);
            const float al0 = exp2f(m0 - mn0), al1 = exp2f(m1 - mn1);
            m0 = mn0; m1 = mn1;
            float rs0 = 0.0f, rs1 = 0.0f;
            #pragma unroll
            for (int nf = 0; nf < 8; nf++) {
                s[nf][0] = exp2f(s[nf][0] - mn0);
                s[nf][1] = exp2f(s[nf][1] - mn0);
                s[nf][2] = exp2f(s[nf][2] - mn1);
                s[nf][3] = exp2f(s[nf][3] - mn1);
                rs0 += s[nf][0] + s[nf][1];
                rs1 += s[nf][2] + s[nf][3];
            }
            rs0 += __shfl_xor_sync(~0u, rs0, 1);
            rs0 += __shfl_xor_sync(~0u, rs0, 2);
            rs1 += __shfl_xor_sync(~0u, rs1, 1);
            rs1 += __shfl_xor_sync(~0u, rs1, 2);
            l0 = l0 * al0 + rs0;
            l1 = l1 * al1 + rs1;
            #pragma unroll
            for (int nf = 0; nf < 8; nf++) {
                o[nf][0] *= al0; o[nf][1] *= al0;
                o[nf][2] *= al1; o[nf][3] *= al1;
            }

            // ---- O += P V (3-term split) ----
            #pragma unroll
            for (int ks = 0; ks < 4; ks++) {
                uint32_t aph[4], apl[4];
                #pragma unroll
                for (int half = 0; half < 2; half++) {
                    const int nf = 2 * ks + half;
                    __nv_bfloat16 hA = __float2bfloat16(s[nf][0]);
                    __nv_bfloat16 hB = __float2bfloat16(s[nf][1]);
                    __nv_bfloat16 hC = __float2bfloat16(s[nf][2]);
                    __nv_bfloat16 hD = __float2bfloat16(s[nf][3]);
                    aph[half*2+0] = pack_bf16(hA, hB);
                    aph[half*2+1] = pack_bf16(hC, hD);
                    apl[half*2+0] = pack_bf16(
                        __float2bfloat16(s[nf][0] - __bfloat162float(hA)),
                        __float2bfloat16(s[nf][1] - __bfloat162float(hB)));
                    apl[half*2+1] = pack_bf16(
                        __float2bfloat16(s[nf][2] - __bfloat162float(hC)),
                        __float2bfloat16(s[nf][3] - __bfloat162float(hD)));
                }
                #pragma unroll
                for (int q = 0; q < 4; q++) {
                    const uint32_t voff = SMEM_SWIZZLE_128B((ks * 16 + vr) * 128 + q * 32 + vcB);
                    uint32_t vh[4], vl[4];
                    ldmx4t(vh, kvb + 16384 + voff);
                    ldmx4t(vl, kvb + 24576 + voff);
                    mma_bf16(o[2*q],   aph, vh);
                    mma_bf16(o[2*q],   aph, vl);
                    mma_bf16(o[2*q],   apl, vh);
                    mma_bf16(o[2*q+1], aph, vh + 2);
                    mma_bf16(o[2*q+1], aph, vl + 2);
                    mma_bf16(o[2*q+1], apl, vh + 2);
                }
            }
        }
    }

    // Epilogue: normalize, split hi/lo, scatter to (B, L, D)
    const int b = bh >> 4, h = bh & 15;
    const float inv0 = 1.0f / l0, inv1 = 1.0f / l1;
    const int lg0 = qb * 128 + wid * 16 + r0, lg1 = lg0 + 8;
    #pragma unroll
    for (int nf = 0; nf < 8; nf++) {
        const int d = h * 64 + nf * 8 + 2 * (lane & 3);
        const size_t i0 = ((size_t)b * LL + lg0) * DD + d;
        const size_t i1 = ((size_t)b * LL + lg1) * DD + d;
        float a0 = o[nf][0] * inv0, a1 = o[nf][1] * inv0;
        float b0_ = o[nf][2] * inv1, b1_ = o[nf][3] * inv1;
        __nv_bfloat16 h00 = __float2bfloat16(a0), h01 = __float2bfloat16(a1);
        __nv_bfloat16 h10 = __float2bfloat16(b0_), h11 = __float2bfloat16(b1_);
        *(__nv_bfloat162*)(Ohi + i0) = __nv_bfloat162(h00, h01);
        *(__nv_bfloat162*)(Ohi + i1) = __nv_bfloat162(h10, h11);
        *(__nv_bfloat162*)(Olo + i0) = __nv_bfloat162(
            __float2bfloat16(a0 - __bfloat162float(h00)),
            __float2bfloat16(a1 - __bfloat162float(h01)));
        *(__nv_bfloat162*)(Olo + i1) = __nv_bfloat162(
            __float2bfloat16(b0_ - __bfloat162float(h10)),
            __float2bfloat16(b1_ - __bfloat162float(h11)));
    }
}

// ---------------------------------------------------------------------------
extern "C" void kernel_launch(void* const* d_in, const int* in_sizes, int n_in,
                              void* d_out, int out_size) {
    (void)in_sizes; (void)n_in; (void)out_size;
    const float* x  = (const float*)d_in[0];
    const float* wq = (const float*)d_in[1];
    const float* bq = (const float*)d_in[2];
    const float* wk = (const float*)d_in[3];
    const float* bk = (const float*)d_in[4];
    const float* wv = (const float*)d_in[5];
    const float* bv = (const float*)d_in[6];
    const float* wo = (const float*)d_in[7];
    const float* bo = (const float*)d_in[8];

    __nv_bfloat16 *xhi, *xlo, *whi, *wlo;
    __nv_bfloat16 *qhi, *qlo, *khi, *klo, *vhi, *vlo, *ohi, *olo;
    cudaGetSymbolAddress((void**)&xhi, g_xhi);
    cudaGetSymbolAddress((void**)&xlo, g_xlo);
    cudaGetSymbolAddress((void**)&whi, g_whi);
    cudaGetSymbolAddress((void**)&wlo, g_wlo);
    cudaGetSymbolAddress((void**)&qhi, g_qhi);
    cudaGetSymbolAddress((void**)&qlo, g_qlo);
    cudaGetSymbolAddress((void**)&khi, g_khi);
    cudaGetSymbolAddress((void**)&klo, g_klo);
    cudaGetSymbolAddress((void**)&vhi, g_vhi);
    cudaGetSymbolAddress((void**)&vlo, g_vlo);
    cudaGetSymbolAddress((void**)&ohi, g_ohi);
    cudaGetSymbolAddress((void**)&olo, g_olo);

    split_all<<<8192, 256>>>(x, wq, wk, wv, wo, xhi, xlo, whi, wlo);

    cudaFuncSetAttribute(mm_gemm<0>, cudaFuncAttributeMaxDynamicSharedMemorySize, GEMM_SMEM);
    cudaFuncSetAttribute(mm_gemm<1>, cudaFuncAttributeMaxDynamicSharedMemorySize, GEMM_SMEM);
    cudaFuncSetAttribute(attn_mma, cudaFuncAttributeMaxDynamicSharedMemorySize, ATT_SMEM);

    // Fused Q,K,V projection: grid (32, 24)
    mm_gemm<1><<<dim3(MTOT / 128, 24), 256, GEMM_SMEM>>>(
        xhi, xlo, whi, wlo, bq, bk, bv, nullptr,
        qhi, qlo, khi, klo, vhi, vlo);

    attn_mma<<<dim3(LL / 128, BB * HH), 256, ATT_SMEM>>>(qhi, qlo, khi, klo,
                                                         vhi, vlo, ohi, olo);

    // Output projection
    mm_gemm<0><<<dim3(MTOT / 128, DD / 128), 256, GEMM_SMEM>>>(
        ohi, olo, whi + 3*DD*DD, wlo + 3*DD*DD, bo, nullptr, nullptr, (float*)d_out,
        nullptr, nullptr, nullptr, nullptr, nullptr, nullptr);
}

// round 8
// speedup vs baseline: 1.0054x; 1.0054x over previous
#include <cuda_runtime.h>
#include <cuda_bf16.h>
#include <cstdint>

// Problem constants
#define BB 2
#define LL 2048
#define DD 1024
#define HH 16
#define DKH 64
#define MTOT (BB*LL)   // 4096

// ---------------------------------------------------------------------------
// Scratch (no cudaMalloc allowed) — all bf16 hi/lo split pairs
// ---------------------------------------------------------------------------
__device__ __nv_bfloat16 g_xhi[MTOT*DD], g_xlo[MTOT*DD];
__device__ __nv_bfloat16 g_whi[4*DD*DD], g_wlo[4*DD*DD];
__device__ __nv_bfloat16 g_qhi[BB*HH*LL*DKH], g_qlo[BB*HH*LL*DKH];
__device__ __nv_bfloat16 g_khi[BB*HH*LL*DKH], g_klo[BB*HH*LL*DKH];
__device__ __nv_bfloat16 g_vhi[BB*HH*LL*DKH], g_vlo[BB*HH*LL*DKH];
__device__ __nv_bfloat16 g_ohi[MTOT*DD], g_olo[MTOT*DD];

__device__ __forceinline__ uint32_t smem_to_u32(const void* p) {
    uint32_t a;
    asm("{ .reg .u64 t; cvta.to.shared.u64 t, %1; cvt.u32.u64 %0, t; }" : "=r"(a) : "l"(p));
    return a;
}
#define SMEM_SWIZZLE_128B(o) ((o) ^ (((o) >> 3) & 0x70))

#define CP_ASYNC16(dst_u32, gptr) \
    asm volatile("cp.async.cg.shared.global [%0], [%1], 16;" \
                 :: "r"(dst_u32), "l"(gptr) : "memory")
#define CP_COMMIT() asm volatile("cp.async.commit_group;" ::: "memory")
#define CP_WAIT0()  asm volatile("cp.async.wait_group 0;" ::: "memory")
#define CP_WAIT1()  asm volatile("cp.async.wait_group 1;" ::: "memory")

__device__ __forceinline__ void ldmx4(uint32_t* r, uint32_t addr) {
    asm volatile("ldmatrix.sync.aligned.m8n8.x4.shared.b16 {%0,%1,%2,%3}, [%4];"
                 : "=r"(r[0]), "=r"(r[1]), "=r"(r[2]), "=r"(r[3]) : "r"(addr));
}
__device__ __forceinline__ void ldmx4t(uint32_t* r, uint32_t addr) {
    asm volatile("ldmatrix.sync.aligned.m8n8.x4.trans.shared.b16 {%0,%1,%2,%3}, [%4];"
                 : "=r"(r[0]), "=r"(r[1]), "=r"(r[2]), "=r"(r[3]) : "r"(addr));
}
__device__ __forceinline__ void mma_bf16(float* c, const uint32_t* a, const uint32_t* b) {
    asm volatile("mma.sync.aligned.m16n8k16.row.col.f32.bf16.bf16.f32 "
                 "{%0,%1,%2,%3}, {%4,%5,%6,%7}, {%8,%9}, {%0,%1,%2,%3};"
                 : "+f"(c[0]), "+f"(c[1]), "+f"(c[2]), "+f"(c[3])
                 : "r"(a[0]), "r"(a[1]), "r"(a[2]), "r"(a[3]), "r"(b[0]), "r"(b[1]));
}
__device__ __forceinline__ uint32_t pack_bf16(__nv_bfloat16 x, __nv_bfloat16 y) {
    __nv_bfloat162 h; h.x = x; h.y = y;
    uint32_t u; __builtin_memcpy(&u, &h, 4);
    return u;
}

// ---------------------------------------------------------------------------
// Fused fp32 -> bf16 hi/lo split for x + 4 weights (one launch)
// ---------------------------------------------------------------------------
__global__ void split_all(const float* __restrict__ x,
                          const float* __restrict__ wq, const float* __restrict__ wk,
                          const float* __restrict__ wv, const float* __restrict__ wo,
                          __nv_bfloat16* __restrict__ xhi, __nv_bfloat16* __restrict__ xlo,
                          __nv_bfloat16* __restrict__ whi, __nv_bfloat16* __restrict__ wlo) {
    const int bid = blockIdx.x;
    const float* src;
    __nv_bfloat16 *hi, *lo;
    int i;
    if (bid < 4096) {
        src = x; hi = xhi; lo = xlo;
        i = bid * 256 + threadIdx.x;
    } else {
        const int wsel = (bid - 4096) >> 10;
        const int lb   = (bid - 4096) & 1023;
        src = (wsel == 0) ? wq : (wsel == 1) ? wk : (wsel == 2) ? wv : wo;
        hi = whi + (size_t)wsel * DD * DD;
        lo = wlo + (size_t)wsel * DD * DD;
        i = lb * 256 + threadIdx.x;
    }
    float4 v = ((const float4*)src)[i];
    __nv_bfloat16 h0 = __float2bfloat16(v.x), h1 = __float2bfloat16(v.y);
    __nv_bfloat16 h2 = __float2bfloat16(v.z), h3 = __float2bfloat16(v.w);
    ((__nv_bfloat162*)hi)[i*2+0] = __nv_bfloat162(h0, h1);
    ((__nv_bfloat162*)hi)[i*2+1] = __nv_bfloat162(h2, h3);
    ((__nv_bfloat162*)lo)[i*2+0] = __nv_bfloat162(
        __float2bfloat16(v.x - __bfloat162float(h0)),
        __float2bfloat16(v.y - __bfloat162float(h1)));
    ((__nv_bfloat162*)lo)[i*2+1] = __nv_bfloat162(
        __float2bfloat16(v.z - __bfloat162float(h2)),
        __float2bfloat16(v.w - __bfloat162float(h3)));
}

// ---------------------------------------------------------------------------
// mma.sync bf16 GEMM, 3-term split. CTA 128x128, BK=32, 3-stage cp.async.
// smem row (128B) = [32 bf16 hi | 32 bf16 lo]; stage (32KB): A@0 B@16K.
// A-fragment double-buffering across mf hides LDSM latency.
// MODE 1: fused QKV (blockIdx.y 0..23). MODE 0: fp32 C row-major.
// ---------------------------------------------------------------------------
#define GEMM_SMEM (3*32768)
#define NCHUNK 32

template<int MODE>
__global__ void __launch_bounds__(256, 2) mm_gemm(
        const __nv_bfloat16* __restrict__ Ahi, const __nv_bfloat16* __restrict__ Alo,
        const __nv_bfloat16* __restrict__ WhiB, const __nv_bfloat16* __restrict__ WloB,
        const float* __restrict__ bias0, const float* __restrict__ bias1,
        const float* __restrict__ bias2, float* __restrict__ C,
        __nv_bfloat16* __restrict__ c0hi, __nv_bfloat16* __restrict__ c0lo,
        __nv_bfloat16* __restrict__ c1hi, __nv_bfloat16* __restrict__ c1lo,
        __nv_bfloat16* __restrict__ c2hi, __nv_bfloat16* __restrict__ c2lo) {
    extern __shared__ char sm[];
    const uint32_t sbase = smem_to_u32(sm);

    const int tid  = threadIdx.x;
    const int wid  = tid >> 5, lane = tid & 31;
    const int wm   = wid & 1, wn = wid >> 1;
    const int mBase = blockIdx.x * 128;

    int nBase, wsel = 0;
    const __nv_bfloat16 *Bhi, *Blo;
    const float* bias;
    if (MODE == 1) {
        wsel  = blockIdx.y >> 3;
        nBase = (blockIdx.y & 7) * 128;
        Bhi = WhiB + (size_t)wsel * DD * DD;
        Blo = WloB + (size_t)wsel * DD * DD;
        bias = (wsel == 0) ? bias0 : (wsel == 1) ? bias1 : bias2;
    } else {
        nBase = blockIdx.y * 128;
        Bhi = WhiB; Blo = WloB; bias = bias0;
    }

    float acc[4][4][4] = {};

    const int aRow = (lane & 15);
    const int aKb  = (lane >> 4) * 16;
    const int bRow = ((lane >> 4) & 1) * 8 + (lane & 7);
    const int bKb  = ((lane >> 3) & 1) * 16;

    auto issue_chunk = [&](int k0, int st) {
        #pragma unroll
        for (int it = 0; it < 8; it++) {
            const int u = it * 256 + tid;
            const int t = u >> 10, idx = u & 1023;
            const int row = idx >> 3, seg = idx & 7;
            const __nv_bfloat16* g;
            if (t == 0) g = ((seg < 4) ? Ahi : Alo) + (size_t)(mBase + row) * DD;
            else        g = ((seg < 4) ? Bhi : Blo) + (size_t)(nBase + row) * DD;
            const uint32_t d = sbase + st * 32768 + t * 16384
                             + SMEM_SWIZZLE_128B(row * 128 + seg * 16);
            CP_ASYNC16(d, g + k0 + (seg & 3) * 8);
        }
    };

    issue_chunk(0, 0);
    CP_COMMIT();
    issue_chunk(32, 1);
    CP_COMMIT();

    int stC = 0, stI = 2;
    for (int c = 0; c < NCHUNK; c++) {
        if (c == NCHUNK - 1) CP_WAIT0(); else CP_WAIT1();
        __syncthreads();
        if (c + 2 < NCHUNK) {
            issue_chunk((c + 2) * 32, stI);
            CP_COMMIT();
            if (++stI == 3) stI = 0;
        }
        const uint32_t sb0 = sbase + stC * 32768;
        if (++stC == 3) stC = 0;

        #pragma unroll
        for (int ks = 0; ks < 2; ks++) {
            uint32_t bh[4][2], bl[4][2];
            #pragma unroll
            for (int p = 0; p < 2; p++) {
                const uint32_t bb = (wn * 32 + p * 16 + bRow) * 128 + ks * 32 + bKb;
                uint32_t r[4];
                ldmx4(r, sb0 + 16384 + SMEM_SWIZZLE_128B(bb));
                bh[p*2+0][0] = r[0]; bh[p*2+0][1] = r[1];
                bh[p*2+1][0] = r[2]; bh[p*2+1][1] = r[3];
                ldmx4(r, sb0 + 16384 + SMEM_SWIZZLE_128B(bb + 64));
                bl[p*2+0][0] = r[0]; bl[p*2+0][1] = r[1];
                bl[p*2+1][0] = r[2]; bl[p*2+1][1] = r[3];
            }
            // A-fragment double buffer across mf
            uint32_t aF[2][2][4];
            {
                const uint32_t ab = (wm * 64 + aRow) * 128 + ks * 32 + aKb;
                ldmx4(aF[0][0], sb0 + SMEM_SWIZZLE_128B(ab));
                ldmx4(aF[0][1], sb0 + SMEM_SWIZZLE_128B(ab + 64));
            }
            #pragma unroll
            for (int mf = 0; mf < 4; mf++) {
                const int cur = mf & 1;
                if (mf < 3) {
                    const uint32_t ab = (wm * 64 + (mf + 1) * 16 + aRow) * 128 + ks * 32 + aKb;
                    ldmx4(aF[cur ^ 1][0], sb0 + SMEM_SWIZZLE_128B(ab));
                    ldmx4(aF[cur ^ 1][1], sb0 + SMEM_SWIZZLE_128B(ab + 64));
                }
                #pragma unroll
                for (int nf = 0; nf < 4; nf++) {
                    mma_bf16(acc[mf][nf], aF[cur][0], bh[nf]);
                    mma_bf16(acc[mf][nf], aF[cur][0], bl[nf]);
                    mma_bf16(acc[mf][nf], aF[cur][1], bh[nf]);
                }
            }
        }
    }

    __nv_bfloat16 *Chi = nullptr, *Clo = nullptr;
    if (MODE == 1) {
        Chi = (wsel == 0) ? c0hi : (wsel == 1) ? c1hi : c2hi;
        Clo = (wsel == 0) ? c0lo : (wsel == 1) ? c1lo : c2lo;
    }

    const int rEp = lane >> 2, cEp = (lane & 3) * 2;
    #pragma unroll
    for (int mf = 0; mf < 4; mf++) {
        #pragma unroll
        for (int nf = 0; nf < 4; nf++) {
            const int m0 = mBase + wm * 64 + mf * 16 + rEp;
            const int n  = nBase + wn * 32 + nf * 8 + cEp;
            const float b0 = bias[n], b1 = bias[n + 1];
            float2 v0 = make_float2(acc[mf][nf][0] + b0, acc[mf][nf][1] + b1);
            float2 v1 = make_float2(acc[mf][nf][2] + b0, acc[mf][nf][3] + b1);
            if (MODE == 0) {
                *(float2*)(C + (size_t)m0 * DD + n) = v0;
                *(float2*)(C + (size_t)(m0 + 8) * DD + n) = v1;
            } else {
                const int h = n >> 6, dk = n & 63;
                const int b_ = m0 / LL, l0 = m0 % LL, l1 = l0 + 8;
                const size_t i0 = (((size_t)b_ * HH + h) * LL + l0) * DKH + dk;
                const size_t i1 = (((size_t)b_ * HH + h) * LL + l1) * DKH + dk;
                __nv_bfloat16 h00 = __float2bfloat16(v0.x), h01 = __float2bfloat16(v0.y);
                __nv_bfloat16 h10 = __float2bfloat16(v1.x), h11 = __float2bfloat16(v1.y);
                *(__nv_bfloat162*)(Chi + i0) = __nv_bfloat162(h00, h01);
                *(__nv_bfloat162*)(Chi + i1) = __nv_bfloat162(h10, h11);
                *(__nv_bfloat162*)(Clo + i0) = __nv_bfloat162(
                    __float2bfloat16(v0.x - __bfloat162float(h00)),
                    __float2bfloat16(v0.y - __bfloat162float(h01)));
                *(__nv_bfloat162*)(Clo + i1) = __nv_bfloat162(
                    __float2bfloat16(v1.x - __bfloat162float(h10)),
                    __float2bfloat16(v1.y - __bfloat162float(h11)));
            }
        }
    }
}

// ---------------------------------------------------------------------------
// Tensor-core causal flash attention, cp.async 2-stage K/V pipeline,
// K/V fragment double-buffering. BQ=128, BKV=64, 8 warps.
// smem: Qhi@0 Qlo@16K; stage s at 32K+s*32K: Khi@+0 Klo@+8K Vhi@+16K Vlo@+24K
// ---------------------------------------------------------------------------
#define ATT_SMEM (32768 + 2*32768)
#define SCL2 0.18033688011112042f   // (1/8) * log2(e)

__global__ void __launch_bounds__(256, 2) attn_mma(
        const __nv_bfloat16* __restrict__ Qhi, const __nv_bfloat16* __restrict__ Qlo,
        const __nv_bfloat16* __restrict__ Khi, const __nv_bfloat16* __restrict__ Klo,
        const __nv_bfloat16* __restrict__ Vhi, const __nv_bfloat16* __restrict__ Vlo,
        __nv_bfloat16* __restrict__ Ohi, __nv_bfloat16* __restrict__ Olo) {
    extern __shared__ char sm[];
    const uint32_t sb = smem_to_u32(sm);

    const int tid = threadIdx.x, wid = tid >> 5, lane = tid & 31;
    const int qb = blockIdx.x, bh = blockIdx.y;

    auto issue_kv = [&](int kb, int st) {
        #pragma unroll
        for (int it = 0; it < 8; it++) {
            const int u = it * 256 + tid;
            const int arr = u >> 9, idx = u & 511;
            const int row = idx >> 3, seg = idx & 7;
            const __nv_bfloat16* src = (arr == 0) ? Khi : (arr == 1) ? Klo
                                     : (arr == 2) ? Vhi : Vlo;
            const uint32_t d = sb + 32768 + st * 32768 + arr * 8192
                             + SMEM_SWIZZLE_128B(row * 128 + seg * 16);
            CP_ASYNC16(d, src + ((size_t)bh * LL + kb * 64 + row) * DKH + seg * 8);
        }
    };

    #pragma unroll
    for (int it = 0; it < 8; it++) {
        const int u = it * 256 + tid;
        const int arr = u >> 10, idx = u & 1023;
        const int row = idx >> 3, seg = idx & 7;
        const __nv_bfloat16* src = arr ? Qlo : Qhi;
        const uint32_t d = sb + arr * 16384 + SMEM_SWIZZLE_128B(row * 128 + seg * 16);
        CP_ASYNC16(d, src + ((size_t)bh * LL + qb * 128 + row) * DKH + seg * 8);
    }
    issue_kv(0, 0);
    CP_COMMIT();

    float s[8][4];
    float o[8][4] = {};
    float m0 = -1e30f, m1 = -1e30f, l0 = 0.0f, l1 = 0.0f;

    const int r0 = lane >> 2;
    const int ig0 = qb * 128 + wid * 16 + r0, ig1 = ig0 + 8;
    const int aRow = lane & 15;
    const int aKb  = (lane >> 4) * 16;
    const int bRow = ((lane >> 4) & 1) * 8 + (lane & 7);
    const int bKb  = ((lane >> 3) & 1) * 16;
    const int vseg = lane >> 3;
    const int vr   = (vseg & 1) * 8 + (lane & 7);
    const int vcB  = (vseg >> 1) * 16;

    const int kbmax = 2 * qb + 1;
    for (int kb = 0; kb <= kbmax; kb++) {
        CP_WAIT0();
        __syncthreads();
        if (kb < kbmax) {
            issue_kv(kb + 1, (kb + 1) & 1);
            CP_COMMIT();
        }

        const bool skip = (kb * 64 > qb * 128 + wid * 16 + 15);
        if (!skip) {
            const uint32_t kvb = sb + 32768 + (kb & 1) * 32768;

            // ---- S = Q K^T (3-term split), K-frag double buffer across p ----
            #pragma unroll
            for (int nf = 0; nf < 8; nf++)
                s[nf][0] = s[nf][1] = s[nf][2] = s[nf][3] = 0.0f;
            #pragma unroll
            for (int ks = 0; ks < 4; ks++) {
                const uint32_t aoff = SMEM_SWIZZLE_128B((wid * 16 + aRow) * 128 + ks * 32 + aKb);
                uint32_t ah[4], al[4];
                ldmx4(ah, sb + aoff);
                ldmx4(al, sb + 16384 + aoff);
                uint32_t kF[2][2][4];
                {
                    const uint32_t b0off = SMEM_SWIZZLE_128B(bRow * 128 + ks * 32 + bKb);
                    ldmx4(kF[0][0], kvb + b0off);
                    ldmx4(kF[0][1], kvb + 8192 + b0off);
                }
                #pragma unroll
                for (int p = 0; p < 4; p++) {
                    const int cur = p & 1;
                    if (p < 3) {
                        const uint32_t bn = SMEM_SWIZZLE_128B(
                            ((p + 1) * 16 + bRow) * 128 + ks * 32 + bKb);
                        ldmx4(kF[cur ^ 1][0], kvb + bn);
                        ldmx4(kF[cur ^ 1][1], kvb + 8192 + bn);
                    }
                    mma_bf16(s[2*p],   ah, kF[cur][0]);
                    mma_bf16(s[2*p],   ah, kF[cur][1]);
                    mma_bf16(s[2*p],   al, kF[cur][0]);
                    mma_bf16(s[2*p+1], ah, kF[cur][0] + 2);
                    mma_bf16(s[2*p+1], ah, kF[cur][1] + 2);
                    mma_bf16(s[2*p+1], al, kF[cur][0] + 2);
                }
            }

            // ---- online softmax in exp2 domain (quad shuffles) ----
            const bool needMask = (kb >= 2 * qb);
            float mx0 = -1e30f, mx1 = -1e30f;
            #pragma unroll
            for (int nf = 0; nf < 8; nf++) {
                #pragma unroll
                for (int c = 0; c < 4; c++) {
                    float v = s[nf][c] * SCL2;
                    if (needMask) {
                        const int jg = kb * 64 + nf * 8 + 2 * (lane & 3) + (c & 1);
                        if (jg > ((c < 2) ? ig0 : ig1)) v = -1e30f;
                    }
                    s[nf][c] = v;
                }
                mx0 = fmaxf(mx0, fmaxf(s[nf][0], s[nf][1]));
                mx1 = fmaxf(mx1, fmaxf(s[nf][2], s[nf][3]));
            }
            mx0 = fmaxf(mx0, __shfl_xor_sync(~0u, mx0, 1));
            mx0 = fmaxf(mx0, __shfl_xor_sync(~0u, mx0, 2));
            mx1 = fmaxf(mx1, __shfl_xor_sync(~0u, mx1, 1));
            mx1 = fmaxf(mx1, __shfl_xor_sync(~0u, mx1, 2));
            const float mn0 = fmaxf(m0, mx0), mn1 = fmaxf(m1, mx1);
            const float al0 = exp2f(m0 - mn0), al1 = exp2f(m1 - mn1);
            m0 = mn0; m1 = mn1;
            float rs0 = 0.0f, rs1 = 0.0f;
            #pragma unroll
            for (int nf = 0; nf < 8; nf++) {
                s[nf][0] = exp2f(s[nf][0] - mn0);
                s[nf][1] = exp2f(s[nf][1] - mn0);
                s[nf][2] = exp2f(s[nf][2] - mn1);
                s[nf][3] = exp2f(s[nf][3] - mn1);
                rs0 += s[nf][0] + s[nf][1];
                rs1 += s[nf][2] + s[nf][3];
            }
            rs0 += __shfl_xor_sync(~0u, rs0, 1);
            rs0 += __shfl_xor_sync(~0u, rs0, 2);
            rs1 += __shfl_xor_sync(~0u, rs1, 1);
            rs1 += __shfl_xor_sync(~0u, rs1, 2);
            l0 = l0 * al0 + rs0;
            l1 = l1 * al1 + rs1;
            #pragma unroll
            for (int nf = 0; nf < 8; nf++) {
                o[nf][0] *= al0; o[nf][1] *= al0;
                o[nf][2] *= al1; o[nf][3] *= al1;
            }

            // ---- O += P V (3-term split), V-frag double buffer across q ----
            #pragma unroll
            for (int ks = 0; ks < 4; ks++) {
                uint32_t aph[4], apl[4];
                #pragma unroll
                for (int half = 0; half < 2; half++) {
                    const int nf = 2 * ks + half;
                    __nv_bfloat16 hA = __float2bfloat16(s[nf][0]);
                    __nv_bfloat16 hB = __float2bfloat16(s[nf][1]);
                    __nv_bfloat16 hC = __float2bfloat16(s[nf][2]);
                    __nv_bfloat16 hD = __float2bfloat16(s[nf][3]);
                    aph[half*2+0] = pack_bf16(hA, hB);
                    aph[half*2+1] = pack_bf16(hC, hD);
                    apl[half*2+0] = pack_bf16(
                        __float2bfloat16(s[nf][0] - __bfloat162float(hA)),
                        __float2bfloat16(s[nf][1] - __bfloat162float(hB)));
                    apl[half*2+1] = pack_bf16(
                        __float2bfloat16(s[nf][2] - __bfloat162float(hC)),
                        __float2bfloat16(s[nf][3] - __bfloat162float(hD)));
                }
                uint32_t vF[2][2][4];
                {
                    const uint32_t v0off = SMEM_SWIZZLE_128B((ks * 16 + vr) * 128 + vcB);
                    ldmx4t(vF[0][0], kvb + 16384 + v0off);
                    ldmx4t(vF[0][1], kvb + 24576 + v0off);
                }
                #pragma unroll
                for (int q = 0; q < 4; q++) {
                    const int cur = q & 1;
                    if (q < 3) {
                        const uint32_t vn = SMEM_SWIZZLE_128B(
                            (ks * 16 + vr) * 128 + (q + 1) * 32 + vcB);
                        ldmx4t(vF[cur ^ 1][0], kvb + 16384 + vn);
                        ldmx4t(vF[cur ^ 1][1], kvb + 24576 + vn);
                    }
                    mma_bf16(o[2*q],   aph, vF[cur][0]);
                    mma_bf16(o[2*q],   aph, vF[cur][1]);
                    mma_bf16(o[2*q],   apl, vF[cur][0]);
                    mma_bf16(o[2*q+1], aph, vF[cur][0] + 2);
                    mma_bf16(o[2*q+1], aph, vF[cur][1] + 2);
                    mma_bf16(o[2*q+1], apl, vF[cur][0] + 2);
                }
            }
        }
    }

    // Epilogue: normalize, split hi/lo, scatter to (B, L, D)
    const int b = bh >> 4, h = bh & 15;
    const float inv0 = 1.0f / l0, inv1 = 1.0f / l1;
    const int lg0 = qb * 128 + wid * 16 + r0, lg1 = lg0 + 8;
    #pragma unroll
    for (int nf = 0; nf < 8; nf++) {
        const int d = h * 64 + nf * 8 + 2 * (lane & 3);
        const size_t i0 = ((size_t)b * LL + lg0) * DD + d;
        const size_t i1 = ((size_t)b * LL + lg1) * DD + d;
        float a0 = o[nf][0] * inv0, a1 = o[nf][1] * inv0;
        float b0_ = o[nf][2] * inv1, b1_ = o[nf][3] * inv1;
        __nv_bfloat16 h00 = __float2bfloat16(a0), h01 = __float2bfloat16(a1);
        __nv_bfloat16 h10 = __float2bfloat16(b0_), h11 = __float2bfloat16(b1_);
        *(__nv_bfloat162*)(Ohi + i0) = __nv_bfloat162(h00, h01);
        *(__nv_bfloat162*)(Ohi + i1) = __nv_bfloat162(h10, h11);
        *(__nv_bfloat162*)(Olo + i0) = __nv_bfloat162(
            __float2bfloat16(a0 - __bfloat162float(h00)),
            __float2bfloat16(a1 - __bfloat162float(h01)));
        *(__nv_bfloat162*)(Olo + i1) = __nv_bfloat162(
            __float2bfloat16(b0_ - __bfloat162float(h10)),
            __float2bfloat16(b1_ - __bfloat162float(h11)));
    }
}

// ---------------------------------------------------------------------------
extern "C" void kernel_launch(void* const* d_in, const int* in_sizes, int n_in,
                              void* d_out, int out_size) {
    (void)in_sizes; (void)n_in; (void)out_size;
    const float* x  = (const float*)d_in[0];
    const float* wq = (const float*)d_in[1];
    const float* bq = (const float*)d_in[2];
    const float* wk = (const float*)d_in[3];
    const float* bk = (const float*)d_in[4];
    const float* wv = (const float*)d_in[5];
    const float* bv = (const float*)d_in[6];
    const float* wo = (const float*)d_in[7];
    const float* bo = (const float*)d_in[8];

    __nv_bfloat16 *xhi, *xlo, *whi, *wlo;
    __nv_bfloat16 *qhi, *qlo, *khi, *klo, *vhi, *vlo, *ohi, *olo;
    cudaGetSymbolAddress((void**)&xhi, g_xhi);
    cudaGetSymbolAddress((void**)&xlo, g_xlo);
    cudaGetSymbolAddress((void**)&whi, g_whi);
    cudaGetSymbolAddress((void**)&wlo, g_wlo);
    cudaGetSymbolAddress((void**)&qhi, g_qhi);
    cudaGetSymbolAddress((void**)&qlo, g_qlo);
    cudaGetSymbolAddress((void**)&khi, g_khi);
    cudaGetSymbolAddress((void**)&klo, g_klo);
    cudaGetSymbolAddress((void**)&vhi, g_vhi);
    cudaGetSymbolAddress((void**)&vlo, g_vlo);
    cudaGetSymbolAddress((void**)&ohi, g_ohi);
    cudaGetSymbolAddress((void**)&olo, g_olo);

    split_all<<<8192, 256>>>(x, wq, wk, wv, wo, xhi, xlo, whi, wlo);

    cudaFuncSetAttribute(mm_gemm<0>, cudaFuncAttributeMaxDynamicSharedMemorySize, GEMM_SMEM);
    cudaFuncSetAttribute(mm_gemm<1>, cudaFuncAttributeMaxDynamicSharedMemorySize, GEMM_SMEM);
    cudaFuncSetAttribute(attn_mma, cudaFuncAttributeMaxDynamicSharedMemorySize, ATT_SMEM);

    // Fused Q,K,V projection: grid (32, 24)
    mm_gemm<1><<<dim3(MTOT / 128, 24), 256, GEMM_SMEM>>>(
        xhi, xlo, whi, wlo, bq, bk, bv, nullptr,
        qhi, qlo, khi, klo, vhi, vlo);

    attn_mma<<<dim3(LL / 128, BB * HH), 256, ATT_SMEM>>>(qhi, qlo, khi, klo,
                                                         vhi, vlo, ohi, olo);

    // Output projection
    mm_gemm<0><<<dim3(MTOT / 128, DD / 128), 256, GEMM_SMEM>>>(
        ohi, olo, whi + 3*DD*DD, wlo + 3*DD*DD, bo, nullptr, nullptr, (float*)d_out,
        nullptr, nullptr, nullptr, nullptr, nullptr, nullptr);
}

// round 9
// speedup vs baseline: 2.3227x; 2.3101x over previous
#include <cuda_runtime.h>
#include <cuda_fp16.h>
#include <cstdint>

// Problem constants
#define BB 2
#define LL 2048
#define DD 1024
#define HH 16
#define DKH 64
#define MTOT (BB*LL)   // 4096

// ---------------------------------------------------------------------------
// Scratch (no cudaMalloc allowed) — fp16 operands
// ---------------------------------------------------------------------------
__device__ __half g_xh[MTOT*DD];
__device__ __half g_wh[4*DD*DD];
__device__ __half g_q[BB*HH*LL*DKH];
__device__ __half g_k[BB*HH*LL*DKH];
__device__ __half g_v[BB*HH*LL*DKH];
__device__ __half g_oh[MTOT*DD];

__device__ __forceinline__ uint32_t smem_to_u32(const void* p) {
    uint32_t a;
    asm("{ .reg .u64 t; cvta.to.shared.u64 t, %1; cvt.u32.u64 %0, t; }" : "=r"(a) : "l"(p));
    return a;
}
#define SMEM_SWIZZLE_128B(o) ((o) ^ (((o) >> 3) & 0x70))

#define CP_ASYNC16(dst_u32, gptr) \
    asm volatile("cp.async.cg.shared.global [%0], [%1], 16;" \
                 :: "r"(dst_u32), "l"(gptr) : "memory")
#define CP_COMMIT() asm volatile("cp.async.commit_group;" ::: "memory")
#define CP_WAIT0()  asm volatile("cp.async.wait_group 0;" ::: "memory")
#define CP_WAIT1()  asm volatile("cp.async.wait_group 1;" ::: "memory")

__device__ __forceinline__ void ldmx4(uint32_t* r, uint32_t addr) {
    asm volatile("ldmatrix.sync.aligned.m8n8.x4.shared.b16 {%0,%1,%2,%3}, [%4];"
                 : "=r"(r[0]), "=r"(r[1]), "=r"(r[2]), "=r"(r[3]) : "r"(addr));
}
__device__ __forceinline__ void ldmx4t(uint32_t* r, uint32_t addr) {
    asm volatile("ldmatrix.sync.aligned.m8n8.x4.trans.shared.b16 {%0,%1,%2,%3}, [%4];"
                 : "=r"(r[0]), "=r"(r[1]), "=r"(r[2]), "=r"(r[3]) : "r"(addr));
}
__device__ __forceinline__ void mma_f16(float* c, const uint32_t* a, const uint32_t* b) {
    asm volatile("mma.sync.aligned.m16n8k16.row.col.f32.f16.f16.f32 "
                 "{%0,%1,%2,%3}, {%4,%5,%6,%7}, {%8,%9}, {%0,%1,%2,%3};"
                 : "+f"(c[0]), "+f"(c[1]), "+f"(c[2]), "+f"(c[3])
                 : "r"(a[0]), "r"(a[1]), "r"(a[2]), "r"(a[3]), "r"(b[0]), "r"(b[1]));
}
__device__ __forceinline__ uint32_t pack_f16(float x, float y) {
    __half2 h = __floats2half2_rn(x, y);
    uint32_t u; __builtin_memcpy(&u, &h, 4);
    return u;
}

// ---------------------------------------------------------------------------
// Fused fp32 -> fp16 convert for x + 4 weights (one launch)
// ---------------------------------------------------------------------------
__global__ void convert_all(const float* __restrict__ x,
                            const float* __restrict__ wq, const float* __restrict__ wk,
                            const float* __restrict__ wv, const float* __restrict__ wo,
                            __half* __restrict__ xh, __half* __restrict__ wh) {
    const int bid = blockIdx.x;
    const float* src;
    __half* dst;
    int i;
    if (bid < 4096) {
        src = x; dst = xh;
        i = bid * 256 + threadIdx.x;
    } else {
        const int wsel = (bid - 4096) >> 10;
        const int lb   = (bid - 4096) & 1023;
        src = (wsel == 0) ? wq : (wsel == 1) ? wk : (wsel == 2) ? wv : wo;
        dst = wh + (size_t)wsel * DD * DD;
        i = lb * 256 + threadIdx.x;
    }
    float4 v = ((const float4*)src)[i];
    ((__half2*)dst)[i*2+0] = __floats2half2_rn(v.x, v.y);
    ((__half2*)dst)[i*2+1] = __floats2half2_rn(v.z, v.w);
}

// ---------------------------------------------------------------------------
// fp16 mma.sync GEMM. CTA 128x128, BK=64 (128B rows), 3-stage cp.async.
// stage (32KB): A@0 (16KB), B@16KB. 8 warps (2M x 4N), warp 64x32.
// MODE 1: fused QKV (blockIdx.y 0..23). MODE 0: fp32 C row-major.
// ---------------------------------------------------------------------------
#define GEMM_SMEM (3*32768)
#define NCHUNK 16

template<int MODE>
__global__ void __launch_bounds__(256, 2) mm_gemm(
        const __half* __restrict__ A, const __half* __restrict__ WB,
        const float* __restrict__ bias0, const float* __restrict__ bias1,
        const float* __restrict__ bias2, float* __restrict__ C,
        __half* __restrict__ c0, __half* __restrict__ c1, __half* __restrict__ c2) {
    extern __shared__ char sm[];
    const uint32_t sbase = smem_to_u32(sm);

    const int tid  = threadIdx.x;
    const int wid  = tid >> 5, lane = tid & 31;
    const int wm   = wid & 1, wn = wid >> 1;
    const int mBase = blockIdx.x * 128;

    int nBase, wsel = 0;
    const __half* B;
    const float* bias;
    if (MODE == 1) {
        wsel  = blockIdx.y >> 3;
        nBase = (blockIdx.y & 7) * 128;
        B = WB + (size_t)wsel * DD * DD;
        bias = (wsel == 0) ? bias0 : (wsel == 1) ? bias1 : bias2;
    } else {
        nBase = blockIdx.y * 128;
        B = WB; bias = bias0;
    }

    float acc[4][4][4] = {};

    const int aRow = (lane & 15);
    const int aKb  = (lane >> 4) * 16;
    const int bRow = ((lane >> 4) & 1) * 8 + (lane & 7);
    const int bKb  = ((lane >> 3) & 1) * 16;

    // loader: 2 tiles x 128 rows x 8 segs(16B) = 2048 / 256 thr = 8 per thread
    auto issue_chunk = [&](int k0, int st) {
        #pragma unroll
        for (int it = 0; it < 8; it++) {
            const int u = it * 256 + tid;
            const int t = u >> 10, idx = u & 1023;
            const int row = idx >> 3, seg = idx & 7;
            const __half* g = (t ? B + (size_t)(nBase + row) * DD
                                 : A + (size_t)(mBase + row) * DD);
            const uint32_t d = sbase + st * 32768 + t * 16384
                             + SMEM_SWIZZLE_128B(row * 128 + seg * 16);
            CP_ASYNC16(d, g + k0 + seg * 8);
        }
    };

    issue_chunk(0, 0);
    CP_COMMIT();
    issue_chunk(64, 1);
    CP_COMMIT();

    int stC = 0, stI = 2;
    for (int c = 0; c < NCHUNK; c++) {
        if (c == NCHUNK - 1) CP_WAIT0(); else CP_WAIT1();
        __syncthreads();
        if (c + 2 < NCHUNK) {
            issue_chunk((c + 2) * 64, stI);
            CP_COMMIT();
            if (++stI == 3) stI = 0;
        }
        const uint32_t sb0 = sbase + stC * 32768;
        if (++stC == 3) stC = 0;

        #pragma unroll
        for (int ks = 0; ks < 4; ks++) {
            uint32_t bF[4][2];
            #pragma unroll
            for (int p = 0; p < 2; p++) {
                const uint32_t bb = (wn * 32 + p * 16 + bRow) * 128 + ks * 32 + bKb;
                uint32_t r[4];
                ldmx4(r, sb0 + 16384 + SMEM_SWIZZLE_128B(bb));
                bF[p*2+0][0] = r[0]; bF[p*2+0][1] = r[1];
                bF[p*2+1][0] = r[2]; bF[p*2+1][1] = r[3];
            }
            #pragma unroll
            for (int mf = 0; mf < 4; mf++) {
                const uint32_t ab = (wm * 64 + mf * 16 + aRow) * 128 + ks * 32 + aKb;
                uint32_t aF[4];
                ldmx4(aF, sb0 + SMEM_SWIZZLE_128B(ab));
                #pragma unroll
                for (int nf = 0; nf < 4; nf++)
                    mma_f16(acc[mf][nf], aF, bF[nf]);
            }
        }
    }

    __half* Ch = nullptr;
    if (MODE == 1) Ch = (wsel == 0) ? c0 : (wsel == 1) ? c1 : c2;

    const int rEp = lane >> 2, cEp = (lane & 3) * 2;
    #pragma unroll
    for (int mf = 0; mf < 4; mf++) {
        #pragma unroll
        for (int nf = 0; nf < 4; nf++) {
            const int m0 = mBase + wm * 64 + mf * 16 + rEp;
            const int n  = nBase + wn * 32 + nf * 8 + cEp;
            const float b0 = bias[n], b1 = bias[n + 1];
            float2 v0 = make_float2(acc[mf][nf][0] + b0, acc[mf][nf][1] + b1);
            float2 v1 = make_float2(acc[mf][nf][2] + b0, acc[mf][nf][3] + b1);
            if (MODE == 0) {
                *(float2*)(C + (size_t)m0 * DD + n) = v0;
                *(float2*)(C + (size_t)(m0 + 8) * DD + n) = v1;
            } else {
                const int h = n >> 6, dk = n & 63;
                const int b_ = m0 / LL, l0 = m0 % LL, l1 = l0 + 8;
                const size_t i0 = (((size_t)b_ * HH + h) * LL + l0) * DKH + dk;
                const size_t i1 = (((size_t)b_ * HH + h) * LL + l1) * DKH + dk;
                *(__half2*)(Ch + i0) = __floats2half2_rn(v0.x, v0.y);
                *(__half2*)(Ch + i1) = __floats2half2_rn(v1.x, v1.y);
            }
        }
    }
}

// ---------------------------------------------------------------------------
// fp16 tensor-core causal flash attention, cp.async 2-stage K/V pipeline.
// BQ=128, BKV=64, 8 warps (16 rows each).
// smem: Q@0 (16KB); stage s at 16K+s*16K: K@+0 (8KB), V@+8K (8KB). Total 48KB.
// ---------------------------------------------------------------------------
#define ATT_SMEM (16384 + 2*16384)
#define SCL2 0.18033688011112042f   // (1/8) * log2(e)

__global__ void __launch_bounds__(256, 2) attn_mma(
        const __half* __restrict__ Q, const __half* __restrict__ K,
        const __half* __restrict__ V, __half* __restrict__ O) {
    extern __shared__ char sm[];
    const uint32_t sb = smem_to_u32(sm);

    const int tid = threadIdx.x, wid = tid >> 5, lane = tid & 31;
    const int qb = blockIdx.x, bh = blockIdx.y;

    auto issue_kv = [&](int kb, int st) {
        #pragma unroll
        for (int it = 0; it < 4; it++) {
            const int u = it * 256 + tid;
            const int arr = u >> 9, idx = u & 511;
            const int row = idx >> 3, seg = idx & 7;
            const __half* src = arr ? V : K;
            const uint32_t d = sb + 16384 + st * 16384 + arr * 8192
                             + SMEM_SWIZZLE_128B(row * 128 + seg * 16);
            CP_ASYNC16(d, src + ((size_t)bh * LL + kb * 64 + row) * DKH + seg * 8);
        }
    };

    // Q tile: 128 rows x 64 fp16 = 16KB
    #pragma unroll
    for (int it = 0; it < 4; it++) {
        const int u = it * 256 + tid;
        const int row = u >> 3, seg = u & 7;
        const uint32_t d = sb + SMEM_SWIZZLE_128B(row * 128 + seg * 16);
        CP_ASYNC16(d, Q + ((size_t)bh * LL + qb * 128 + row) * DKH + seg * 8);
    }
    issue_kv(0, 0);
    CP_COMMIT();

    float s[8][4];
    float o[8][4] = {};
    float m0 = -1e30f, m1 = -1e30f, l0 = 0.0f, l1 = 0.0f;

    const int r0 = lane >> 2;
    const int ig0 = qb * 128 + wid * 16 + r0, ig1 = ig0 + 8;
    const int aRow = lane & 15;
    const int aKb  = (lane >> 4) * 16;
    const int bRow = ((lane >> 4) & 1) * 8 + (lane & 7);
    const int bKb  = ((lane >> 3) & 1) * 16;
    const int vseg = lane >> 3;
    const int vr   = (vseg & 1) * 8 + (lane & 7);
    const int vcB  = (vseg >> 1) * 16;

    const int kbmax = 2 * qb + 1;
    for (int kb = 0; kb <= kbmax; kb++) {
        CP_WAIT0();
        __syncthreads();
        if (kb < kbmax) {
            issue_kv(kb + 1, (kb + 1) & 1);
            CP_COMMIT();
        }

        const bool skip = (kb * 64 > qb * 128 + wid * 16 + 15);
        if (!skip) {
            const uint32_t kvb = sb + 16384 + (kb & 1) * 16384;

            // ---- S = Q K^T ----
            #pragma unroll
            for (int nf = 0; nf < 8; nf++)
                s[nf][0] = s[nf][1] = s[nf][2] = s[nf][3] = 0.0f;
            #pragma unroll
            for (int ks = 0; ks < 4; ks++) {
                const uint32_t aoff = SMEM_SWIZZLE_128B((wid * 16 + aRow) * 128 + ks * 32 + aKb);
                uint32_t ah[4];
                ldmx4(ah, sb + aoff);
                #pragma unroll
                for (int p = 0; p < 4; p++) {
                    const uint32_t boff = SMEM_SWIZZLE_128B((p * 16 + bRow) * 128 + ks * 32 + bKb);
                    uint32_t rh[4];
                    ldmx4(rh, kvb + boff);
                    mma_f16(s[2*p],   ah, rh);
                    mma_f16(s[2*p+1], ah, rh + 2);
                }
            }

            // ---- online softmax in exp2 domain (quad shuffles) ----
            const bool needMask = (kb >= 2 * qb);
            float mx0 = -1e30f, mx1 = -1e30f;
            #pragma unroll
            for (int nf = 0; nf < 8; nf++) {
                #pragma unroll
                for (int c = 0; c < 4; c++) {
                    float v = s[nf][c] * SCL2;
                    if (needMask) {
                        const int jg = kb * 64 + nf * 8 + 2 * (lane & 3) + (c & 1);
                        if (jg > ((c < 2) ? ig0 : ig1)) v = -1e30f;
                    }
                    s[nf][c] = v;
                }
                mx0 = fmaxf(mx0, fmaxf(s[nf][0], s[nf][1]));
                mx1 = fmaxf(mx1, fmaxf(s[nf][2], s[nf][3]));
            }
            mx0 = fmaxf(mx0, __shfl_xor_sync(~0u, mx0, 1));
            mx0 = fmaxf(mx0, __shfl_xor_sync(~0u, mx0, 2));
            mx1 = fmaxf(mx1, __shfl_xor_sync(~0u, mx1, 1));
            mx1 = fmaxf(mx1, __shfl_xor_sync(~0u, mx1, 2));
            const float mn0 = fmaxf(m0, mx0), mn1 = fmaxf(m1, mx1);
            const float al0 = exp2f(m0 - mn0), al1 = exp2f(m1 - mn1);
            m0 = mn0; m1 = mn1;
            float rs0 = 0.0f, rs1 = 0.0f;
            #pragma unroll
            for (int nf = 0; nf < 8; nf++) {
                s[nf][0] = exp2f(s[nf][0] - mn0);
                s[nf][1] = exp2f(s[nf][1] - mn0);
                s[nf][2] = exp2f(s[nf][2] - mn1);
                s[nf][3] = exp2f(s[nf][3] - mn1);
                rs0 += s[nf][0] + s[nf][1];
                rs1 += s[nf][2] + s[nf][3];
            }
            rs0 += __shfl_xor_sync(~0u, rs0, 1);
            rs0 += __shfl_xor_sync(~0u, rs0, 2);
            rs1 += __shfl_xor_sync(~0u, rs1, 1);
            rs1 += __shfl_xor_sync(~0u, rs1, 2);
            l0 = l0 * al0 + rs0;
            l1 = l1 * al1 + rs1;
            #pragma unroll
            for (int nf = 0; nf < 8; nf++) {
                o[nf][0] *= al0; o[nf][1] *= al0;
                o[nf][2] *= al1; o[nf][3] *= al1;
            }

            // ---- O += P V ----
            #pragma unroll
            for (int ks = 0; ks < 4; ks++) {
                uint32_t aph[4];
                aph[0] = pack_f16(s[2*ks][0],   s[2*ks][1]);
                aph[1] = pack_f16(s[2*ks][2],   s[2*ks][3]);
                aph[2] = pack_f16(s[2*ks+1][0], s[2*ks+1][1]);
                aph[3] = pack_f16(s[2*ks+1][2], s[2*ks+1][3]);
                #pragma unroll
                for (int q = 0; q < 4; q++) {
                    const uint32_t voff = SMEM_SWIZZLE_128B((ks * 16 + vr) * 128 + q * 32 + vcB);
                    uint32_t vh[4];
                    ldmx4t(vh, kvb + 8192 + voff);
                    mma_f16(o[2*q],   aph, vh);
                    mma_f16(o[2*q+1], aph, vh + 2);
                }
            }
        }
    }

    // Epilogue: normalize, convert fp16, scatter to (B, L, D)
    const int b = bh >> 4, h = bh & 15;
    const float inv0 = 1.0f / l0, inv1 = 1.0f / l1;
    const int lg0 = qb * 128 + wid * 16 + r0, lg1 = lg0 + 8;
    #pragma unroll
    for (int nf = 0; nf < 8; nf++) {
        const int d = h * 64 + nf * 8 + 2 * (lane & 3);
        const size_t i0 = ((size_t)b * LL + lg0) * DD + d;
        const size_t i1 = ((size_t)b * LL + lg1) * DD + d;
        *(__half2*)(O + i0) = __floats2half2_rn(o[nf][0] * inv0, o[nf][1] * inv0);
        *(__half2*)(O + i1) = __floats2half2_rn(o[nf][2] * inv1, o[nf][3] * inv1);
    }
}

// ---------------------------------------------------------------------------
extern "C" void kernel_launch(void* const* d_in, const int* in_sizes, int n_in,
                              void* d_out, int out_size) {
    (void)in_sizes; (void)n_in; (void)out_size;
    const float* x  = (const float*)d_in[0];
    const float* wq = (const float*)d_in[1];
    const float* bq = (const float*)d_in[2];
    const float* wk = (const float*)d_in[3];
    const float* bk = (const float*)d_in[4];
    const float* wv = (const float*)d_in[5];
    const float* bv = (const float*)d_in[6];
    const float* wo = (const float*)d_in[7];
    const float* bo = (const float*)d_in[8];

    __half *xh, *wh, *q, *k, *v, *oh;
    cudaGetSymbolAddress((void**)&xh, g_xh);
    cudaGetSymbolAddress((void**)&wh, g_wh);
    cudaGetSymbolAddress((void**)&q,  g_q);
    cudaGetSymbolAddress((void**)&k,  g_k);
    cudaGetSymbolAddress((void**)&v,  g_v);
    cudaGetSymbolAddress((void**)&oh, g_oh);

    convert_all<<<8192, 256>>>(x, wq, wk, wv, wo, xh, wh);

    cudaFuncSetAttribute(mm_gemm<0>, cudaFuncAttributeMaxDynamicSharedMemorySize, GEMM_SMEM);
    cudaFuncSetAttribute(mm_gemm<1>, cudaFuncAttributeMaxDynamicSharedMemorySize, GEMM_SMEM);
    cudaFuncSetAttribute(attn_mma, cudaFuncAttributeMaxDynamicSharedMemorySize, ATT_SMEM);

    // Fused Q,K,V projection: grid (32, 24)
    mm_gemm<1><<<dim3(MTOT / 128, 24), 256, GEMM_SMEM>>>(
        xh, wh, bq, bk, bv, nullptr, q, k, v);

    attn_mma<<<dim3(LL / 128, BB * HH), 256, ATT_SMEM>>>(q, k, v, oh);

    // Output projection
    mm_gemm<0><<<dim3(MTOT / 128, DD / 128), 256, GEMM_SMEM>>>(
        oh, wh + 3*(size_t)DD*DD, bo, nullptr, nullptr, (float*)d_out,
        nullptr, nullptr, nullptr);
}

// round 10
// speedup vs baseline: 2.3837x; 1.0263x over previous
#include <cuda_runtime.h>
#include <cuda_fp16.h>
#include <cstdint>

// Problem constants
#define BB 2
#define LL 2048
#define DD 1024
#define HH 16
#define DKH 64
#define MTOT (BB*LL)   // 4096

// ---------------------------------------------------------------------------
// Scratch (no cudaMalloc allowed) — fp16 operands
// ---------------------------------------------------------------------------
__device__ __half g_xh[MTOT*DD];
__device__ __half g_wh[4*DD*DD];
__device__ __half g_q[BB*HH*LL*DKH];
__device__ __half g_k[BB*HH*LL*DKH];
__device__ __half g_v[BB*HH*LL*DKH];
__device__ __half g_oh[MTOT*DD];

__device__ __forceinline__ uint32_t smem_to_u32(const void* p) {
    uint32_t a;
    asm("{ .reg .u64 t; cvta.to.shared.u64 t, %1; cvt.u32.u64 %0, t; }" : "=r"(a) : "l"(p));
    return a;
}
#define SMEM_SWIZZLE_128B(o) ((o) ^ (((o) >> 3) & 0x70))

#define CP_ASYNC16(dst_u32, gptr) \
    asm volatile("cp.async.cg.shared.global [%0], [%1], 16;" \
                 :: "r"(dst_u32), "l"(gptr) : "memory")
#define CP_COMMIT() asm volatile("cp.async.commit_group;" ::: "memory")
#define CP_WAIT0()  asm volatile("cp.async.wait_group 0;" ::: "memory")
#define CP_WAIT1()  asm volatile("cp.async.wait_group 1;" ::: "memory")

__device__ __forceinline__ void ldmx4(uint32_t* r, uint32_t addr) {
    asm volatile("ldmatrix.sync.aligned.m8n8.x4.shared.b16 {%0,%1,%2,%3}, [%4];"
                 : "=r"(r[0]), "=r"(r[1]), "=r"(r[2]), "=r"(r[3]) : "r"(addr));
}
__device__ __forceinline__ void ldmx4t(uint32_t* r, uint32_t addr) {
    asm volatile("ldmatrix.sync.aligned.m8n8.x4.trans.shared.b16 {%0,%1,%2,%3}, [%4];"
                 : "=r"(r[0]), "=r"(r[1]), "=r"(r[2]), "=r"(r[3]) : "r"(addr));
}
__device__ __forceinline__ void mma_f16(float* c, const uint32_t* a, const uint32_t* b) {
    asm volatile("mma.sync.aligned.m16n8k16.row.col.f32.f16.f16.f32 "
                 "{%0,%1,%2,%3}, {%4,%5,%6,%7}, {%8,%9}, {%0,%1,%2,%3};"
                 : "+f"(c[0]), "+f"(c[1]), "+f"(c[2]), "+f"(c[3])
                 : "r"(a[0]), "r"(a[1]), "r"(a[2]), "r"(a[3]), "r"(b[0]), "r"(b[1]));
}
__device__ __forceinline__ uint32_t pack_f16(float x, float y) {
    __half2 h = __floats2half2_rn(x, y);
    uint32_t u; __builtin_memcpy(&u, &h, 4);
    return u;
}

// ---------------------------------------------------------------------------
// Fused fp32 -> fp16 convert for x + 4 weights (one launch)
// ---------------------------------------------------------------------------
__global__ void convert_all(const float* __restrict__ x,
                            const float* __restrict__ wq, const float* __restrict__ wk,
                            const float* __restrict__ wv, const float* __restrict__ wo,
                            __half* __restrict__ xh, __half* __restrict__ wh) {
    const int bid = blockIdx.x;
    const float* src;
    __half* dst;
    int i;
    if (bid < 4096) {
        src = x; dst = xh;
        i = bid * 256 + threadIdx.x;
    } else {
        const int wsel = (bid - 4096) >> 10;
        const int lb   = (bid - 4096) & 1023;
        src = (wsel == 0) ? wq : (wsel == 1) ? wk : (wsel == 2) ? wv : wo;
        dst = wh + (size_t)wsel * DD * DD;
        i = lb * 256 + threadIdx.x;
    }
    float4 v = ((const float4*)src)[i];
    ((__half2*)dst)[i*2+0] = __floats2half2_rn(v.x, v.y);
    ((__half2*)dst)[i*2+1] = __floats2half2_rn(v.z, v.w);
}

// ---------------------------------------------------------------------------
// fp16 mma.sync GEMM. CTA 128x128, BK=64 (128B rows), 3-stage cp.async,
// A/B fragment software pipelining across flattened (ks, mf) loop.
// MODE 1: fused QKV (blockIdx.y 0..23). MODE 0: fp32 C row-major.
// ---------------------------------------------------------------------------
#define GEMM_SMEM (3*32768)
#define NCHUNK 16

template<int MODE>
__global__ void __launch_bounds__(256, 2) mm_gemm(
        const __half* __restrict__ A, const __half* __restrict__ WB,
        const float* __restrict__ bias0, const float* __restrict__ bias1,
        const float* __restrict__ bias2, float* __restrict__ C,
        __half* __restrict__ c0, __half* __restrict__ c1, __half* __restrict__ c2) {
    extern __shared__ char sm[];
    const uint32_t sbase = smem_to_u32(sm);

    const int tid  = threadIdx.x;
    const int wid  = tid >> 5, lane = tid & 31;
    const int wm   = wid & 1, wn = wid >> 1;
    const int mBase = blockIdx.x * 128;

    int nBase, wsel = 0;
    const __half* B;
    const float* bias;
    if (MODE == 1) {
        wsel  = blockIdx.y >> 3;
        nBase = (blockIdx.y & 7) * 128;
        B = WB + (size_t)wsel * DD * DD;
        bias = (wsel == 0) ? bias0 : (wsel == 1) ? bias1 : bias2;
    } else {
        nBase = blockIdx.y * 128;
        B = WB; bias = bias0;
    }

    float acc[4][4][4] = {};

    const int aRow = (lane & 15);
    const int aKb  = (lane >> 4) * 16;
    const int bRow = ((lane >> 4) & 1) * 8 + (lane & 7);
    const int bKb  = ((lane >> 3) & 1) * 16;

    auto issue_chunk = [&](int k0, int st) {
        #pragma unroll
        for (int it = 0; it < 8; it++) {
            const int u = it * 256 + tid;
            const int t = u >> 10, idx = u & 1023;
            const int row = idx >> 3, seg = idx & 7;
            const __half* g = (t ? B + (size_t)(nBase + row) * DD
                                 : A + (size_t)(mBase + row) * DD);
            const uint32_t d = sbase + st * 32768 + t * 16384
                             + SMEM_SWIZZLE_128B(row * 128 + seg * 16);
            CP_ASYNC16(d, g + k0 + seg * 8);
        }
    };

    issue_chunk(0, 0);
    CP_COMMIT();
    issue_chunk(64, 1);
    CP_COMMIT();

    int stC = 0, stI = 2;
    for (int c = 0; c < NCHUNK; c++) {
        if (c == NCHUNK - 1) CP_WAIT0(); else CP_WAIT1();
        __syncthreads();
        if (c + 2 < NCHUNK) {
            issue_chunk((c + 2) * 64, stI);
            CP_COMMIT();
            if (++stI == 3) stI = 0;
        }
        const uint32_t sb0 = sbase + stC * 32768;
        if (++stC == 3) stC = 0;

        // Fragment-pipelined mainloop over flattened (ks, mf)
        uint32_t bF[2][4][2], aF[2][4];
        auto loadB = [&](int ks, int buf) {
            #pragma unroll
            for (int p = 0; p < 2; p++) {
                const uint32_t bb = (wn * 32 + p * 16 + bRow) * 128 + ks * 32 + bKb;
                uint32_t r[4];
                ldmx4(r, sb0 + 16384 + SMEM_SWIZZLE_128B(bb));
                bF[buf][p*2+0][0] = r[0]; bF[buf][p*2+0][1] = r[1];
                bF[buf][p*2+1][0] = r[2]; bF[buf][p*2+1][1] = r[3];
            }
        };
        auto loadA = [&](int ks, int mf, int buf) {
            const uint32_t ab = (wm * 64 + mf * 16 + aRow) * 128 + ks * 32 + aKb;
            ldmx4(aF[buf], sb0 + SMEM_SWIZZLE_128B(ab));
        };

        loadB(0, 0);
        loadA(0, 0, 0);
        #pragma unroll
        for (int ks = 0; ks < 4; ks++) {
            const int cb = ks & 1;
            #pragma unroll
            for (int mf = 0; mf < 4; mf++) {
                const int ca = (ks * 4 + mf) & 1;
                if (mf < 3)      loadA(ks, mf + 1, ca ^ 1);
                else if (ks < 3) { loadB(ks + 1, cb ^ 1); loadA(ks + 1, 0, ca ^ 1); }
                #pragma unroll
                for (int nf = 0; nf < 4; nf++)
                    mma_f16(acc[mf][nf], aF[ca], bF[cb][nf]);
            }
        }
    }

    __half* Ch = nullptr;
    if (MODE == 1) Ch = (wsel == 0) ? c0 : (wsel == 1) ? c1 : c2;

    const int rEp = lane >> 2, cEp = (lane & 3) * 2;
    #pragma unroll
    for (int mf = 0; mf < 4; mf++) {
        #pragma unroll
        for (int nf = 0; nf < 4; nf++) {
            const int m0 = mBase + wm * 64 + mf * 16 + rEp;
            const int n  = nBase + wn * 32 + nf * 8 + cEp;
            const float b0 = bias[n], b1 = bias[n + 1];
            float2 v0 = make_float2(acc[mf][nf][0] + b0, acc[mf][nf][1] + b1);
            float2 v1 = make_float2(acc[mf][nf][2] + b0, acc[mf][nf][3] + b1);
            if (MODE == 0) {
                *(float2*)(C + (size_t)m0 * DD + n) = v0;
                *(float2*)(C + (size_t)(m0 + 8) * DD + n) = v1;
            } else {
                const int h = n >> 6, dk = n & 63;
                const int b_ = m0 / LL, l0 = m0 % LL, l1 = l0 + 8;
                const size_t i0 = (((size_t)b_ * HH + h) * LL + l0) * DKH + dk;
                const size_t i1 = (((size_t)b_ * HH + h) * LL + l1) * DKH + dk;
                *(__half2*)(Ch + i0) = __floats2half2_rn(v0.x, v0.y);
                *(__half2*)(Ch + i1) = __floats2half2_rn(v1.x, v1.y);
            }
        }
    }
}

// ---------------------------------------------------------------------------
// fp16 tensor-core causal flash attention, cp.async 2-stage K/V pipeline,
// fragment software pipelining, longest-first CTA order.
// BQ=128, BKV=64, 8 warps (16 rows each).
// smem: Q@0 (16KB); stage s at 16K+s*16K: K@+0 (8KB), V@+8K (8KB). Total 48KB.
// ---------------------------------------------------------------------------
#define ATT_SMEM (16384 + 2*16384)
#define SCL2 0.18033688011112042f   // (1/8) * log2(e)

__global__ void __launch_bounds__(256, 2) attn_mma(
        const __half* __restrict__ Q, const __half* __restrict__ K,
        const __half* __restrict__ V, __half* __restrict__ O) {
    extern __shared__ char sm[];
    const uint32_t sb = smem_to_u32(sm);

    const int tid = threadIdx.x, wid = tid >> 5, lane = tid & 31;
    // longest-first: high qb (most KV tiles) gets lowest blockIdx.x
    const int qb = gridDim.x - 1 - blockIdx.x;
    const int bh = blockIdx.y;

    auto issue_kv = [&](int kb, int st) {
        #pragma unroll
        for (int it = 0; it < 4; it++) {
            const int u = it * 256 + tid;
            const int arr = u >> 9, idx = u & 511;
            const int row = idx >> 3, seg = idx & 7;
            const __half* src = arr ? V : K;
            const uint32_t d = sb + 16384 + st * 16384 + arr * 8192
                             + SMEM_SWIZZLE_128B(row * 128 + seg * 16);
            CP_ASYNC16(d, src + ((size_t)bh * LL + kb * 64 + row) * DKH + seg * 8);
        }
    };

    // Q tile: 128 rows x 64 fp16 = 16KB
    #pragma unroll
    for (int it = 0; it < 4; it++) {
        const int u = it * 256 + tid;
        const int row = u >> 3, seg = u & 7;
        const uint32_t d = sb + SMEM_SWIZZLE_128B(row * 128 + seg * 16);
        CP_ASYNC16(d, Q + ((size_t)bh * LL + qb * 128 + row) * DKH + seg * 8);
    }
    issue_kv(0, 0);
    CP_COMMIT();

    float s[8][4];
    float o[8][4] = {};
    float m0 = -1e30f, m1 = -1e30f, l0 = 0.0f, l1 = 0.0f;

    const int r0 = lane >> 2;
    const int ig0 = qb * 128 + wid * 16 + r0, ig1 = ig0 + 8;
    const int aRow = lane & 15;
    const int aKb  = (lane >> 4) * 16;
    const int bRow = ((lane >> 4) & 1) * 8 + (lane & 7);
    const int bKb  = ((lane >> 3) & 1) * 16;
    const int vseg = lane >> 3;
    const int vr   = (vseg & 1) * 8 + (lane & 7);
    const int vcB  = (vseg >> 1) * 16;

    const int kbmax = 2 * qb + 1;
    for (int kb = 0; kb <= kbmax; kb++) {
        CP_WAIT0();
        __syncthreads();
        if (kb < kbmax) {
            issue_kv(kb + 1, (kb + 1) & 1);
            CP_COMMIT();
        }

        const bool skip = (kb * 64 > qb * 128 + wid * 16 + 15);
        if (!skip) {
            const uint32_t kvb = sb + 16384 + (kb & 1) * 16384;

            // ---- S = Q K^T, fragment-pipelined over flattened (ks, p) ----
            #pragma unroll
            for (int nf = 0; nf < 8; nf++)
                s[nf][0] = s[nf][1] = s[nf][2] = s[nf][3] = 0.0f;
            {
                uint32_t ah[2][4], kF[2][4];
                auto loadQf = [&](int ks, int buf) {
                    const uint32_t ao = SMEM_SWIZZLE_128B((wid * 16 + aRow) * 128 + ks * 32 + aKb);
                    ldmx4(ah[buf], sb + ao);
                };
                auto loadKf = [&](int ks, int p, int buf) {
                    const uint32_t bo = SMEM_SWIZZLE_128B((p * 16 + bRow) * 128 + ks * 32 + bKb);
                    ldmx4(kF[buf], kvb + bo);
                };
                loadQf(0, 0);
                loadKf(0, 0, 0);
                #pragma unroll
                for (int ks = 0; ks < 4; ks++) {
                    const int cq = ks & 1;
                    #pragma unroll
                    for (int p = 0; p < 4; p++) {
                        const int ck = (ks * 4 + p) & 1;
                        if (p < 3)       loadKf(ks, p + 1, ck ^ 1);
                        else if (ks < 3) { loadQf(ks + 1, cq ^ 1); loadKf(ks + 1, 0, ck ^ 1); }
                        mma_f16(s[2*p],   ah[cq], kF[ck]);
                        mma_f16(s[2*p+1], ah[cq], kF[ck] + 2);
                    }
                }
            }

            // ---- online softmax in exp2 domain (quad shuffles) ----
            const bool needMask = (kb >= 2 * qb);
            float mx0 = -1e30f, mx1 = -1e30f;
            #pragma unroll
            for (int nf = 0; nf < 8; nf++) {
                #pragma unroll
                for (int c = 0; c < 4; c++) {
                    float v = s[nf][c] * SCL2;
                    if (needMask) {
                        const int jg = kb * 64 + nf * 8 + 2 * (lane & 3) + (c & 1);
                        if (jg > ((c < 2) ? ig0 : ig1)) v = -1e30f;
                    }
                    s[nf][c] = v;
                }
                mx0 = fmaxf(mx0, fmaxf(s[nf][0], s[nf][1]));
                mx1 = fmaxf(mx1, fmaxf(s[nf][2], s[nf][3]));
            }
            mx0 = fmaxf(mx0, __shfl_xor_sync(~0u, mx0, 1));
            mx0 = fmaxf(mx0, __shfl_xor_sync(~0u, mx0, 2));
            mx1 = fmaxf(mx1, __shfl_xor_sync(~0u, mx1, 1));
            mx1 = fmaxf(mx1, __shfl_xor_sync(~0u, mx1, 2));
            const float mn0 = fmaxf(m0, mx0), mn1 = fmaxf(m1, mx1);
            const float al0 = exp2f(m0 - mn0), al1 = exp2f(m1 - mn1);
            m0 = mn0; m1 = mn1;
            float rs0 = 0.0f, rs1 = 0.0f;
            #pragma unroll
            for (int nf = 0; nf < 8; nf++) {
                s[nf][0] = exp2f(s[nf][0] - mn0);
                s[nf][1] = exp2f(s[nf][1] - mn0);
                s[nf][2] = exp2f(s[nf][2] - mn1);
                s[nf][3] = exp2f(s[nf][3] - mn1);
                rs0 += s[nf][0] + s[nf][1];
                rs1 += s[nf][2] + s[nf][3];
            }
            rs0 += __shfl_xor_sync(~0u, rs0, 1);
            rs0 += __shfl_xor_sync(~0u, rs0, 2);
            rs1 += __shfl_xor_sync(~0u, rs1, 1);
            rs1 += __shfl_xor_sync(~0u, rs1, 2);
            l0 = l0 * al0 + rs0;
            l1 = l1 * al1 + rs1;
            #pragma unroll
            for (int nf = 0; nf < 8; nf++) {
                o[nf][0] *= al0; o[nf][1] *= al0;
                o[nf][2] *= al1; o[nf][3] *= al1;
            }

            // ---- O += P V, V-fragment pipelined ----
            {
                uint32_t vF[2][4];
                auto loadVf = [&](int ks, int q, int buf) {
                    const uint32_t vo = SMEM_SWIZZLE_128B((ks * 16 + vr) * 128 + q * 32 + vcB);
                    ldmx4t(vF[buf], kvb + 8192 + vo);
                };
                loadVf(0, 0, 0);
                #pragma unroll
                for (int ks = 0; ks < 4; ks++) {
                    uint32_t aph[4];
                    aph[0] = pack_f16(s[2*ks][0],   s[2*ks][1]);
                    aph[1] = pack_f16(s[2*ks][2],   s[2*ks][3]);
                    aph[2] = pack_f16(s[2*ks+1][0], s[2*ks+1][1]);
                    aph[3] = pack_f16(s[2*ks+1][2], s[2*ks+1][3]);
                    #pragma unroll
                    for (int q = 0; q < 4; q++) {
                        const int cv = (ks * 4 + q) & 1;
                        if (q < 3)       loadVf(ks, q + 1, cv ^ 1);
                        else if (ks < 3) loadVf(ks + 1, 0, cv ^ 1);
                        mma_f16(o[2*q],   aph, vF[cv]);
                        mma_f16(o[2*q+1], aph, vF[cv] + 2);
                    }
                }
            }
        }
    }

    // Epilogue: normalize, convert fp16, scatter to (B, L, D)
    const int b = bh >> 4, h = bh & 15;
    const float inv0 = 1.0f / l0, inv1 = 1.0f / l1;
    const int lg0 = qb * 128 + wid * 16 + r0, lg1 = lg0 + 8;
    #pragma unroll
    for (int nf = 0; nf < 8; nf++) {
        const int d = h * 64 + nf * 8 + 2 * (lane & 3);
        const size_t i0 = ((size_t)b * LL + lg0) * DD + d;
        const size_t i1 = ((size_t)b * LL + lg1) * DD + d;
        *(__half2*)(O + i0) = __floats2half2_rn(o[nf][0] * inv0, o[nf][1] * inv0);
        *(__half2*)(O + i1) = __floats2half2_rn(o[nf][2] * inv1, o[nf][3] * inv1);
    }
}

// ---------------------------------------------------------------------------
extern "C" void kernel_launch(void* const* d_in, const int* in_sizes, int n_in,
                              void* d_out, int out_size) {
    (void)in_sizes; (void)n_in; (void)out_size;
    const float* x  = (const float*)d_in[0];
    const float* wq = (const float*)d_in[1];
    const float* bq = (const float*)d_in[2];
    const float* wk = (const float*)d_in[3];
    const float* bk = (const float*)d_in[4];
    const float* wv = (const float*)d_in[5];
    const float* bv = (const float*)d_in[6];
    const float* wo = (const float*)d_in[7];
    const float* bo = (const float*)d_in[8];

    __half *xh, *wh, *q, *k, *v, *oh;
    cudaGetSymbolAddress((void**)&xh, g_xh);
    cudaGetSymbolAddress((void**)&wh, g_wh);
    cudaGetSymbolAddress((void**)&q,  g_q);
    cudaGetSymbolAddress((void**)&k,  g_k);
    cudaGetSymbolAddress((void**)&v,  g_v);
    cudaGetSymbolAddress((void**)&oh, g_oh);

    convert_all<<<8192, 256>>>(x, wq, wk, wv, wo, xh, wh);

    cudaFuncSetAttribute(mm_gemm<0>, cudaFuncAttributeMaxDynamicSharedMemorySize, GEMM_SMEM);
    cudaFuncSetAttribute(mm_gemm<1>, cudaFuncAttributeMaxDynamicSharedMemorySize, GEMM_SMEM);
    cudaFuncSetAttribute(attn_mma, cudaFuncAttributeMaxDynamicSharedMemorySize, ATT_SMEM);

    // Fused Q,K,V projection: grid (32, 24)
    mm_gemm<1><<<dim3(MTOT / 128, 24), 256, GEMM_SMEM>>>(
        xh, wh, bq, bk, bv, nullptr, q, k, v);

    attn_mma<<<dim3(LL / 128, BB * HH), 256, ATT_SMEM>>>(q, k, v, oh);

    // Output projection
    mm_gemm<0><<<dim3(MTOT / 128, DD / 128), 256, GEMM_SMEM>>>(
        oh, wh + 3*(size_t)DD*DD, bo, nullptr, nullptr, (float*)d_out,
        nullptr, nullptr, nullptr);
}